// round 12
// baseline (speedup 1.0000x reference)
#include <cuda_runtime.h>
#include <cstdint>
#include <math.h>

#define UU 208
#define VV 176
#define NB (UU*VV)        // 36608
#define NIMG 256
#define KHALF 89          // VV/2 + 1
#define RANK 18304        // 0-indexed median index (numpy/jax 'nearest')

// ---------------- scratch (device globals; no allocation allowed) ----------
__device__ unsigned int g_keys[NB];
__device__ unsigned int g_thr;    // key at sorted rank 18304 (percentile threshold)
__device__ float        g_h[2][KHALF][UU];        // hr, hi
__device__ float        g_Bv[VV][192];            // stage-A basis
__device__ float        g_E[2*KHALF][VV];         // stage-E basis
__device__ float        g_A[2][KHALF][UU][NIMG];  // Ar, Ai
__device__ float        g_Bb[2][KHALF][UU][NIMG]; // Br, Bi

// ---------------- K0: exact spectrum of symmetric 6x6 kernel ---------------
// Integer phase t = (13km + 11ln) mod 2288 with a shared cospi table makes
// all symmetry-related bins BITWISE tied.
__global__ void k0_spectrum(const float* __restrict__ kern) {
    __shared__ double tcs[1145];
    __shared__ double p[6][6];
    for (int j = threadIdx.x; j < 1145; j += blockDim.x)
        tcs[j] = cospi((double)j / 1144.0);
    if (threadIdx.x < 36) {
        int m = threadIdx.x / 6, n = threadIdx.x % 6;
        int mm = m < 3 ? m : 5 - m;
        int nn = n < 3 ? n : 5 - n;
        p[m][n] = (double)kern[mm * 3 + nn];
    }
    __syncthreads();
    int idx = blockIdx.x * blockDim.x + threadIdx.x;
    if (idx >= NB) return;
    int l = idx / VV, k = idx % VV;
    double s = 0.0;
    for (int m = 0; m < 6; m++) {
        int tm = (13 * k * m) % 2288;
        for (int n = 0; n < 6; n++) {
            int t = (tm + 11 * l * n) % 2288;
            int tc = (t > 1144) ? (2288 - t) : t;
            s += p[m][n] * tcs[tc];
        }
    }
    float r = (float)(s / 36.0);
    unsigned u = __float_as_uint(r);
    unsigned key = (u & 0x80000000u) ? ~u : (u | 0x80000000u);
    g_keys[idx] = key;
}

// ---------------- K1: radix-select key at rank 18304 -----------------------
__global__ void k1_select() {
    __shared__ int hist[2048];
    __shared__ unsigned s_pref;
    __shared__ int s_rank;
    int tid = threadIdx.x;
    if (tid == 0) { s_pref = 0u; s_rank = RANK; }
    __syncthreads();
    for (int pass = 0; pass < 3; pass++) {
        int shift = (pass == 0) ? 21 : ((pass == 1) ? 10 : 0);
        int nbins = (pass == 2) ? 1024 : 2048;
        unsigned pmask = (pass == 0) ? 0u : ((pass == 1) ? 0xFFE00000u : 0xFFFFFC00u);
        for (int j = tid; j < 2048; j += blockDim.x) hist[j] = 0;
        __syncthreads();
        unsigned pref = s_pref;
        for (int j = tid; j < NB; j += blockDim.x) {
            unsigned key = g_keys[j];
            if ((key & pmask) == (pref & pmask)) {
                int d = (key >> shift) & (nbins - 1);
                atomicAdd(&hist[d], 1);
            }
        }
        __syncthreads();
        if (tid == 0) {
            int cum = 0, rank = s_rank;
            for (int b = 0; b < nbins; b++) {
                int c = hist[b];
                if (cum + c > rank) {
                    s_pref = pref | ((unsigned)b << shift);
                    s_rank = rank - cum;
                    break;
                }
                cum += c;
            }
        }
        __syncthreads();
    }
    if (tid == 0) g_thr = s_pref;
}

// ---------------- K2a: per-column circulant kernels h_k --------------------
// Weight rule (calibrated through rounds 2/8/9/10): JAX's mask = strict
// greater-than PLUS one twin of the threshold conjugate pair (nT=2). The
// Hermitian representation of that mask gives the T-pair weight 0.5 each;
// the antisymmetric remainder is pure-imaginary -> second order under abs.
__global__ void k2_h() {
    int k = blockIdx.x;          // 0..88
    __shared__ float ct[UU], st[UU], wl[UU];
    int tid = threadIdx.x;
    for (int j = tid; j < UU; j += blockDim.x) {
        float sv, cv;
        sincospif(2.0f * (float)j / (float)UU, &sv, &cv);
        ct[j] = cv; st[j] = sv;
    }
    unsigned thr = g_thr;
    for (int l = tid; l < UU; l += blockDim.x) {
        unsigned key = g_keys[l * VV + k];
        wl[l] = (key > thr) ? 1.0f : ((key == thr) ? 0.5f : 0.0f);
    }
    __syncthreads();
    if (tid < UU) {
        int d = tid;
        float hr = 0.f, hi = 0.f;
        int ph = 0;
        for (int l = 0; l < UU; l++) {
            float wv = wl[l];
            hr += wv * ct[ph];
            hi += wv * st[ph];
            ph += d; if (ph >= UU) ph -= UU;
        }
        g_h[0][k][d] = hr * (1.0f / (float)UU);
        g_h[1][k][d] = hi * (1.0f / (float)UU);
    }
}

// ---------------- K2b: DFT basis matrices for stages A and E ---------------
__global__ void k2_basis() {
    int idx = blockIdx.x * blockDim.x + threadIdx.x;
    const int nBv = VV * 192;
    if (idx < nBv) {
        int n = idx / 192, c = idx % 192;
        if (c >= 178) { g_Bv[n][c] = 0.0f; return; }
        int k = c >> 1;
        int ph = (k * n) % VV;
        float s, cc;
        sincospif(2.0f * (float)ph / (float)VV, &s, &cc);
        g_Bv[n][c] = (c & 1) ? -s : cc;
    } else {
        int j = idx - nBv;
        if (j < 2 * KHALF * VV) {
            int r = j / VV, b = j % VV;
            int k = r >> 1;
            int ph = (k * b) % VV;
            float s, cc;
            sincospif(2.0f * (float)ph / (float)VV, &s, &cc);
            float ckf = (k == 0 || k == KHALF - 1) ? 1.0f : 2.0f;
            float v = (r & 1) ? (-ckf * s) : (ckf * cc);
            g_E[r][b] = v * (1.0f / (float)VV);
        }
    }
}

// ---------------- K3: stage A  (V-forward half-spectrum) -------------------
__global__ __launch_bounds__(256) void k3_stageA(const float* __restrict__ x) {
    extern __shared__ float sm[];
    float* Xs  = sm;                 // [64][177]
    float* Bvs = sm + 64 * 177;      // [176][192]
    int m = blockIdx.x, q = blockIdx.y;
    int tid = threadIdx.x;

    const float* bsrc = &g_Bv[0][0];
    for (int j = tid; j < VV * 192; j += 256) Bvs[j] = bsrc[j];
    for (int j = tid; j < 64 * VV; j += 256) {
        int ii = j / VV, n = j % VV;
        int img = q * 64 + ii;
        Xs[ii * 177 + n] = x[(img * UU + m) * VV + n];
    }
    __syncthreads();

    int ip  = tid & 31;
    int cph = tid >> 5;
    int i0 = ip * 2;

    for (int g = 0; g < 6; g++) {
        int cbase = cph + 32 * g;
        float acc0[4] = {0.f, 0.f, 0.f, 0.f};
        float acc1[4] = {0.f, 0.f, 0.f, 0.f};
        for (int n = 0; n < VV; n++) {
            float x0 = Xs[i0 * 177 + n];
            float x1 = Xs[(i0 + 1) * 177 + n];
            const float* bn = &Bvs[n * 192 + cbase];
#pragma unroll
            for (int t = 0; t < 4; t++) {
                float bv = bn[8 * t];
                acc0[t] += x0 * bv;
                acc1[t] += x1 * bv;
            }
        }
#pragma unroll
        for (int t = 0; t < 4; t++) {
            int c = cbase + 8 * t;
            if (c < 178) {
                int k = c >> 1, ri = c & 1;
                g_A[ri][k][m][q * 64 + i0]     = acc0[t];
                g_A[ri][k][m][q * 64 + i0 + 1] = acc1[t];
            }
        }
    }
}

// ---------------- K4: stage G  (fused U-fwd * mask * U-inv, circulant) -----
__global__ __launch_bounds__(256) void k4_stageG() {
    extern __shared__ float sm[];
    float* hsr = sm;
    float* hsi = sm + UU;
    float* Asr = sm + 2 * UU;          // [208][64]
    float* Asi = Asr + UU * 64;
    int atile = blockIdx.x, itile = blockIdx.y, k = blockIdx.z;
    int tid = threadIdx.x;

    for (int j = tid; j < UU; j += 256) {
        hsr[j] = g_h[0][k][j];
        hsi[j] = g_h[1][k][j];
    }
    for (int j = tid; j < UU * 64; j += 256) {
        int mm = j >> 6, ii = j & 63;
        Asr[j] = g_A[0][k][mm][itile * 64 + ii];
        Asi[j] = g_A[1][k][mm][itile * 64 + ii];
    }
    __syncthreads();

    int a_local = tid >> 4;
    int ig = (tid & 15) << 2;
    int a = atile * 16 + a_local;

    float br0 = 0.f, br1 = 0.f, br2 = 0.f, br3 = 0.f;
    float bi0 = 0.f, bi1 = 0.f, bi2 = 0.f, bi3 = 0.f;
    int d = a;
#pragma unroll 4
    for (int m = 0; m < UU; m++) {
        float hr = hsr[d], hi = hsi[d];
        float4 ar = *(const float4*)&Asr[(m << 6) + ig];
        float4 ai = *(const float4*)&Asi[(m << 6) + ig];
        br0 += hr * ar.x - hi * ai.x;  bi0 += hr * ai.x + hi * ar.x;
        br1 += hr * ar.y - hi * ai.y;  bi1 += hr * ai.y + hi * ar.y;
        br2 += hr * ar.z - hi * ai.z;  bi2 += hr * ai.z + hi * ar.z;
        br3 += hr * ar.w - hi * ai.w;  bi3 += hr * ai.w + hi * ar.w;
        d--; if (d < 0) d += UU;
    }
    int imgbase = itile * 64 + ig;
    *(float4*)&g_Bb[0][k][a][imgbase] = make_float4(br0, br1, br2, br3);
    *(float4*)&g_Bb[1][k][a][imgbase] = make_float4(bi0, bi1, bi2, bi3);
}

// ---------------- K5: stage E  (V-inverse, Hermitian fold) + abs -----------
__global__ __launch_bounds__(256) void k5_stageE(float* __restrict__ out) {
    extern __shared__ float sm[];
    float* Bsr = sm;                     // [89][64]
    float* Bsi = Bsr + KHALF * 64;
    float* Es  = Bsi + KHALF * 64;       // [178][176]
    int a = blockIdx.x, itile = blockIdx.y;
    int tid = threadIdx.x;

    for (int j = tid; j < KHALF * 64; j += 256) {
        int kk = j >> 6, ii = j & 63;
        Bsr[j] = g_Bb[0][kk][a][itile * 64 + ii];
        Bsi[j] = g_Bb[1][kk][a][itile * 64 + ii];
    }
    const float* esrc = &g_E[0][0];
    for (int j = tid; j < 2 * KHALF * VV; j += 256) Es[j] = esrc[j];
    __syncthreads();

    int img_l = tid & 63;
    int bph = tid >> 6;
    int img = itile * 64 + img_l;

    for (int g = 0; g < 11; g++) {
        int b0 = bph * 44 + g * 4;
        float a0 = 0.f, a1 = 0.f, a2 = 0.f, a3 = 0.f;
        for (int k = 0; k < KHALF; k++) {
            float br = Bsr[(k << 6) + img_l];
            float bi = Bsi[(k << 6) + img_l];
            float4 e0 = *(const float4*)&Es[(2 * k) * VV + b0];
            float4 e1 = *(const float4*)&Es[(2 * k + 1) * VV + b0];
            a0 += br * e0.x + bi * e1.x;
            a1 += br * e0.y + bi * e1.y;
            a2 += br * e0.z + bi * e1.z;
            a3 += br * e0.w + bi * e1.w;
        }
        float4 o = make_float4(fabsf(a0), fabsf(a1), fabsf(a2), fabsf(a3));
        *(float4*)&out[(img * UU + a) * VV + b0] = o;
    }
}

// ---------------- launcher -------------------------------------------------
extern "C" void kernel_launch(void* const* d_in, const int* in_sizes, int n_in,
                              void* d_out, int out_size) {
    const float* x = nullptr;
    const float* kern = nullptr;
    for (int i = 0; i < n_in; i++) {
        if (in_sizes[i] == 9) kern = (const float*)d_in[i];
        else if (in_sizes[i] > 1000) x = (const float*)d_in[i];
    }

    const int SM3 = (64 * 177 + VV * 192) * 4;
    const int SM4 = (2 * UU + 2 * UU * 64) * 4;
    const int SM5 = (2 * KHALF * 64 + 2 * KHALF * VV) * 4;
    cudaFuncSetAttribute(k3_stageA, cudaFuncAttributeMaxDynamicSharedMemorySize, SM3);
    cudaFuncSetAttribute(k4_stageG, cudaFuncAttributeMaxDynamicSharedMemorySize, SM4);
    cudaFuncSetAttribute(k5_stageE, cudaFuncAttributeMaxDynamicSharedMemorySize, SM5);

    k0_spectrum<<<(NB + 255) / 256, 256>>>(kern);
    k1_select<<<1, 1024>>>();
    k2_h<<<KHALF, 256>>>();
    {
        int total = VV * 192 + 2 * KHALF * VV;
        k2_basis<<<(total + 255) / 256, 256>>>();
    }
    k3_stageA<<<dim3(UU, 4), 256, SM3>>>(x);
    k4_stageG<<<dim3(13, 4, KHALF), 256, SM4>>>();
    k5_stageE<<<dim3(UU, 4), 256, SM5>>>((float*)d_out);
}

// round 14
// speedup vs baseline: 1.4850x; 1.4850x over previous
#include <cuda_runtime.h>
#include <cstdint>
#include <math.h>

#define UU 208
#define VV 176
#define NB (UU*VV)        // 36608
#define NIMG 256
#define KHALF 89          // VV/2 + 1
#define RANK 18304        // 0-indexed median index (numpy/jax 'nearest')

// ---------------- scratch (device globals; no allocation allowed) ----------
__device__ unsigned int g_keys[NB];
__device__ unsigned int g_thr;    // key at sorted rank 18304 (percentile threshold)
__device__ float        g_h[KHALF][UU][2];        // (hr, hi) interleaved
__device__ float        g_Bv[VV][192];            // stage-A basis (192-padded)
__device__ float        g_E[2*KHALF][VV];         // stage-E basis
__device__ float        g_A[2][KHALF][UU][NIMG];  // Ar, Ai
__device__ float        g_Bb[2][KHALF][UU][NIMG]; // Br, Bi

// ---------------- K0: exact spectrum of symmetric 6x6 kernel ---------------
__global__ void k0_spectrum(const float* __restrict__ kern) {
    __shared__ double tcs[1145];
    __shared__ double p[6][6];
    for (int j = threadIdx.x; j < 1145; j += blockDim.x)
        tcs[j] = cospi((double)j / 1144.0);
    if (threadIdx.x < 36) {
        int m = threadIdx.x / 6, n = threadIdx.x % 6;
        int mm = m < 3 ? m : 5 - m;
        int nn = n < 3 ? n : 5 - n;
        p[m][n] = (double)kern[mm * 3 + nn];
    }
    __syncthreads();
    int idx = blockIdx.x * blockDim.x + threadIdx.x;
    if (idx >= NB) return;
    int l = idx / VV, k = idx % VV;
    double s = 0.0;
    for (int m = 0; m < 6; m++) {
        int tm = (13 * k * m) % 2288;
        for (int n = 0; n < 6; n++) {
            int t = (tm + 11 * l * n) % 2288;
            int tc = (t > 1144) ? (2288 - t) : t;
            s += p[m][n] * tcs[tc];
        }
    }
    float r = (float)(s / 36.0);
    unsigned u = __float_as_uint(r);
    unsigned key = (u & 0x80000000u) ? ~u : (u | 0x80000000u);
    g_keys[idx] = key;
}

// ---------------- K1: radix-select key at rank 18304 -----------------------
__global__ void k1_select() {
    __shared__ int hist[2048];
    __shared__ unsigned s_pref;
    __shared__ int s_rank;
    int tid = threadIdx.x;
    if (tid == 0) { s_pref = 0u; s_rank = RANK; }
    __syncthreads();
    for (int pass = 0; pass < 3; pass++) {
        int shift = (pass == 0) ? 21 : ((pass == 1) ? 10 : 0);
        int nbins = (pass == 2) ? 1024 : 2048;
        unsigned pmask = (pass == 0) ? 0u : ((pass == 1) ? 0xFFE00000u : 0xFFFFFC00u);
        for (int j = tid; j < 2048; j += blockDim.x) hist[j] = 0;
        __syncthreads();
        unsigned pref = s_pref;
        for (int j = tid; j < NB; j += blockDim.x) {
            unsigned key = g_keys[j];
            if ((key & pmask) == (pref & pmask)) {
                int d = (key >> shift) & (nbins - 1);
                atomicAdd(&hist[d], 1);
            }
        }
        __syncthreads();
        if (tid == 0) {
            int cum = 0, rank = s_rank;
            for (int b = 0; b < nbins; b++) {
                int c = hist[b];
                if (cum + c > rank) {
                    s_pref = pref | ((unsigned)b << shift);
                    s_rank = rank - cum;
                    break;
                }
                cum += c;
            }
        }
        __syncthreads();
    }
    if (tid == 0) g_thr = s_pref;
}

// ---------------- K2a: per-column circulant kernels h_k --------------------
// JAX's mask = strict greater-than PLUS one twin of the threshold conjugate
// pair (calibrated rounds 2..10). Hermitian representation: T-pair weight 0.5.
__global__ void k2_h() {
    int k = blockIdx.x;          // 0..88
    __shared__ float ct[UU], st[UU], wl[UU];
    int tid = threadIdx.x;
    for (int j = tid; j < UU; j += blockDim.x) {
        float sv, cv;
        sincospif(2.0f * (float)j / (float)UU, &sv, &cv);
        ct[j] = cv; st[j] = sv;
    }
    unsigned thr = g_thr;
    for (int l = tid; l < UU; l += blockDim.x) {
        unsigned key = g_keys[l * VV + k];
        wl[l] = (key > thr) ? 1.0f : ((key == thr) ? 0.5f : 0.0f);
    }
    __syncthreads();
    if (tid < UU) {
        int d = tid;
        float hr = 0.f, hi = 0.f;
        int ph = 0;
        for (int l = 0; l < UU; l++) {
            float wv = wl[l];
            hr += wv * ct[ph];
            hi += wv * st[ph];
            ph += d; if (ph >= UU) ph -= UU;
        }
        g_h[k][d][0] = hr * (1.0f / (float)UU);
        g_h[k][d][1] = hi * (1.0f / (float)UU);
    }
}

// ---------------- K2b: DFT basis matrices for stages A and E ---------------
__global__ void k2_basis() {
    int idx = blockIdx.x * blockDim.x + threadIdx.x;
    const int nBv = VV * 192;
    if (idx < nBv) {
        int n = idx / 192, c = idx % 192;
        if (c >= 178) { g_Bv[n][c] = 0.0f; return; }
        int k = c >> 1;
        int ph = (k * n) % VV;
        float s, cc;
        sincospif(2.0f * (float)ph / (float)VV, &s, &cc);
        g_Bv[n][c] = (c & 1) ? -s : cc;
    } else {
        int j = idx - nBv;
        if (j < 2 * KHALF * VV) {
            int r = j / VV, b = j % VV;
            int k = r >> 1;
            int ph = (k * b) % VV;
            float s, cc;
            sincospif(2.0f * (float)ph / (float)VV, &s, &cc);
            float ckf = (k == 0 || k == KHALF - 1) ? 1.0f : 2.0f;
            float v = (r & 1) ? (-ckf * s) : (ckf * cc);
            g_E[r][b] = v * (1.0f / (float)VV);
        }
    }
}

// ---------------- K3: stage A (V-forward), 4c x 4img register tile ---------
// grid (208 m, 4 img-tiles), 256 threads.
// smem: Xt[176][68] (transposed, padded) + Bvs[176][64] (c-slice per pass)
__global__ __launch_bounds__(256, 2) void k3_stageA(const float* __restrict__ x) {
    extern __shared__ float sm[];
    float* Xt  = sm;                  // [176][68]
    float* Bvs = sm + 176 * 68;       // [176][64]
    int m = blockIdx.x, itile = blockIdx.y;
    int tid = threadIdx.x;
    int img0 = itile * 64;
    int cgroup = tid >> 4;            // 0..15 -> 4 c each
    int ig = (tid & 15) << 2;         // 0..60 -> 4 img

    // transposed X load: global-coalesced (n contiguous), smem write strided
    for (int j = tid; j < VV * 64; j += 256) {
        int ii = j / VV, n = j - ii * VV;
        Xt[n * 68 + ii] = x[((img0 + ii) * UU + m) * VV + n];
    }

    for (int pass = 0; pass < 3; pass++) {
        int cb = pass * 64;
        for (int j = tid; j < VV * 64; j += 256) {
            int n = j >> 6, cl = j & 63;
            Bvs[j] = g_Bv[n][cb + cl];
        }
        __syncthreads();

        float acc[4][4];
#pragma unroll
        for (int j = 0; j < 4; j++)
#pragma unroll
            for (int t = 0; t < 4; t++) acc[j][t] = 0.f;

        const float* bvp = &Bvs[cgroup * 4];
        const float* xtp = &Xt[ig];
#pragma unroll 4
        for (int n = 0; n < VV; n++) {
            float4 bv = *(const float4*)(bvp + n * 64);
            float4 xv = *(const float4*)(xtp + n * 68);
#pragma unroll
            for (int t = 0; t < 4; t++) {
                acc[0][t] += bv.x * ((const float*)&xv)[t];
                acc[1][t] += bv.y * ((const float*)&xv)[t];
                acc[2][t] += bv.z * ((const float*)&xv)[t];
                acc[3][t] += bv.w * ((const float*)&xv)[t];
            }
        }

#pragma unroll
        for (int j = 0; j < 4; j++) {
            int c = cb + cgroup * 4 + j;
            if (c < 178) {
                int kk = c >> 1, ri = c & 1;
                *(float4*)&g_A[ri][kk][m][img0 + ig] =
                    make_float4(acc[j][0], acc[j][1], acc[j][2], acc[j][3]);
            }
        }
        __syncthreads();
    }
}

// ---------------- K4: stage G (circulant), 4a x 4img register tile ---------
// grid (2 a-halves[104], 4 img-tiles[64], 89 k), 416 threads.
// smem: h2[420] float2 (wrapped) + Asr[208][64] + Asi[208][64]
__global__ __launch_bounds__(416) void k4_stageG() {
    extern __shared__ float sm[];
    float2* h2 = (float2*)sm;              // [420]
    float* Asr = sm + 840;                 // [208][64]
    float* Asi = Asr + UU * 64;            // [208][64]
    int atile = blockIdx.x, itile = blockIdx.y, k = blockIdx.z;
    int tid = threadIdx.x;
    int img0 = itile * 64;
    int agroup = tid >> 4;                 // 0..25 -> 4 a each
    int ig = (tid & 15) << 2;              // 4 img
    int a0 = atile * 104 + agroup * 4;

    const float2* hg = (const float2*)&g_h[k][0][0];
    for (int j = tid; j < 420; j += 416) {
        int d = j; if (d >= UU) d -= UU; if (d >= UU) d -= UU;
        h2[j] = hg[d];
    }
    for (int j = tid; j < UU * 64; j += 416) {
        int mm = j >> 6, ii = j & 63;
        Asr[j] = g_A[0][k][mm][img0 + ii];
        Asi[j] = g_A[1][k][mm][img0 + ii];
    }
    __syncthreads();

    float br[4][4], bi[4][4];
#pragma unroll
    for (int j = 0; j < 4; j++)
#pragma unroll
        for (int t = 0; t < 4; t++) { br[j][t] = 0.f; bi[j][t] = 0.f; }

    int base = a0 + UU;                    // index of h for m=0
#pragma unroll 2
    for (int m = 0; m < UU; m++) {
        float2 h0 = h2[base + 0];
        float2 h1 = h2[base + 1];
        float2 h2v = h2[base + 2];
        float2 h3 = h2[base + 3];
        float4 ar = *(const float4*)&Asr[(m << 6) + ig];
        float4 ai = *(const float4*)&Asi[(m << 6) + ig];
        const float* arp = (const float*)&ar;
        const float* aip = (const float*)&ai;
#pragma unroll
        for (int t = 0; t < 4; t++) {
            float arv = arp[t], aiv = aip[t];
            br[0][t] += h0.x * arv - h0.y * aiv;  bi[0][t] += h0.x * aiv + h0.y * arv;
            br[1][t] += h1.x * arv - h1.y * aiv;  bi[1][t] += h1.x * aiv + h1.y * arv;
            br[2][t] += h2v.x * arv - h2v.y * aiv; bi[2][t] += h2v.x * aiv + h2v.y * arv;
            br[3][t] += h3.x * arv - h3.y * aiv;  bi[3][t] += h3.x * aiv + h3.y * arv;
        }
        base--;
    }

#pragma unroll
    for (int j = 0; j < 4; j++) {
        int a = a0 + j;
        *(float4*)&g_Bb[0][k][a][img0 + ig] =
            make_float4(br[j][0], br[j][1], br[j][2], br[j][3]);
        *(float4*)&g_Bb[1][k][a][img0 + ig] =
            make_float4(bi[j][0], bi[j][1], bi[j][2], bi[j][3]);
    }
}

// ---------------- K5: stage E (V-inverse) + abs, 4b x 4img tile ------------
// grid (208 a, 4 img-tiles), 256 threads.
// smem: Bsr[89][64] + Bsi[89][64] + Ess[178][64] (b-slice per pass)
__global__ __launch_bounds__(256, 2) void k5_stageE(float* __restrict__ out) {
    extern __shared__ float sm[];
    float* Bsr = sm;                        // [89][64]
    float* Bsi = Bsr + KHALF * 64;          // [89][64]
    float* Ess = Bsi + KHALF * 64;          // [178][64]
    int a = blockIdx.x, itile = blockIdx.y;
    int tid = threadIdx.x;
    int img0 = itile * 64;
    int bgroup = tid >> 4;                  // 0..15 -> 4 b each
    int ig = (tid & 15) << 2;               // 4 img

    for (int j = tid; j < KHALF * 64; j += 256) {
        int kk = j >> 6, ii = j & 63;
        Bsr[j] = g_Bb[0][kk][a][img0 + ii];
        Bsi[j] = g_Bb[1][kk][a][img0 + ii];
    }

    for (int pass = 0; pass < 3; pass++) {
        int bb = pass * 64;
        for (int j = tid; j < 2 * KHALF * 64; j += 256) {
            int r = j >> 6, bl = j & 63;
            Ess[j] = (bb + bl < VV) ? g_E[r][bb + bl] : 0.f;
        }
        __syncthreads();

        float acc[4][4];
#pragma unroll
        for (int j = 0; j < 4; j++)
#pragma unroll
            for (int t = 0; t < 4; t++) acc[j][t] = 0.f;

        const float* bp = &Bsr[ig];
        const float* bip = &Bsi[ig];
        const float* ep = &Ess[bgroup * 4];
#pragma unroll 2
        for (int k = 0; k < KHALF; k++) {
            float4 brv = *(const float4*)(bp + (k << 6));
            float4 biv = *(const float4*)(bip + (k << 6));
            float4 e0 = *(const float4*)(ep + (2 * k) * 64);
            float4 e1 = *(const float4*)(ep + (2 * k + 1) * 64);
            const float* brp = (const float*)&brv;
            const float* bipp = (const float*)&biv;
            const float* e0p = (const float*)&e0;
            const float* e1p = (const float*)&e1;
#pragma unroll
            for (int j = 0; j < 4; j++)
#pragma unroll
                for (int t = 0; t < 4; t++)
                    acc[j][t] += brp[t] * e0p[j] + bipp[t] * e1p[j];
        }

        int b0 = bb + bgroup * 4;
        if (b0 < VV) {
#pragma unroll
            for (int t = 0; t < 4; t++) {
                int img = img0 + ig + t;
                float* op = &out[(img * UU + a) * VV + b0];
                op[0] = fabsf(acc[0][t]);
                op[1] = fabsf(acc[1][t]);
                op[2] = fabsf(acc[2][t]);
                op[3] = fabsf(acc[3][t]);
            }
        }
        __syncthreads();
    }
}

// ---------------- launcher -------------------------------------------------
extern "C" void kernel_launch(void* const* d_in, const int* in_sizes, int n_in,
                              void* d_out, int out_size) {
    const float* x = nullptr;
    const float* kern = nullptr;
    for (int i = 0; i < n_in; i++) {
        if (in_sizes[i] == 9) kern = (const float*)d_in[i];
        else if (in_sizes[i] > 1000) x = (const float*)d_in[i];
    }

    const int SM3 = (176 * 68 + 176 * 64) * 4;                 // 92,928 B
    const int SM4 = (840 + 2 * UU * 64) * 4;                   // 109,856 B
    const int SM5 = (2 * KHALF * 64 + 2 * KHALF * 64) * 4;     // 91,136 B
    cudaFuncSetAttribute(k3_stageA, cudaFuncAttributeMaxDynamicSharedMemorySize, SM3);
    cudaFuncSetAttribute(k4_stageG, cudaFuncAttributeMaxDynamicSharedMemorySize, SM4);
    cudaFuncSetAttribute(k5_stageE, cudaFuncAttributeMaxDynamicSharedMemorySize, SM5);

    k0_spectrum<<<(NB + 255) / 256, 256>>>(kern);
    k1_select<<<1, 1024>>>();
    k2_h<<<KHALF, 256>>>();
    {
        int total = VV * 192 + 2 * KHALF * VV;
        k2_basis<<<(total + 255) / 256, 256>>>();
    }
    k3_stageA<<<dim3(UU, 4), 256, SM3>>>(x);
    k4_stageG<<<dim3(2, 4, KHALF), 416, SM4>>>();
    k5_stageE<<<dim3(UU, 4), 256, SM5>>>((float*)d_out);
}